// round 15
// baseline (speedup 1.0000x reference)
#include <cuda_runtime.h>
#include <cstdint>

#define LL 8
#define KK 8
#define NN 1048576
#define GBLK 256            // gram blocks per layer (128 threads each)
#define GTHR 128            // gram block size
#define OBLK 256            // output blocks per layer
#define NPAIR 36            // upper-triangular 8x8 pairs
#define R4C (NN / 4)        // float4 per row = 262144
#define GSTRIDE (GBLK * GTHR) // 32768 float4 per sweep (same as prior rounds)
#define GITERS (R4C / GSTRIDE) // 8
#define HROWS 4             // rows per half-stage
// ring: 3 iterations x 8 rows x 128 thr x 16B = 49152B = 48KB exactly

// Deterministic reduction scratch (no device mallocs allowed).
__device__ float g_part[LL][GBLK][NPAIR];
__device__ float g_w[LL][KK * KK];

// ---------------------------------------------------------------------------
// Kernel 1: per-block partial Gram sums via cp.async (LDGSTS) smem pipeline.
// MLP decoupled from registers: each thread keeps 3 iterations (6 half-stage
// groups, 384B) of 16B async copies in flight with per-thread commit/wait
// groups. 128-thread blocks make the 3-deep ring EXACTLY 48KB dynamic smem
// (the no-attribute limit); zero static smem (reduction scratch aliased into
// the dead ring after the loop). 4 CTAs/SM -> ~196KB/SM bytes in flight.
// Each thread produces AND consumes only its own smem slots -> no
// __syncthreads in the pipeline. Accumulation order bit-identical to prior
// rounds (same n0/GSTRIDE mapping).
// grid = (GBLK, LL), block = 128.
// ---------------------------------------------------------------------------
__global__ __launch_bounds__(GTHR, 4) void gram_kernel(const float* __restrict__ deltas) {
    extern __shared__ float4 buf[];   // [6 half-slots][HROWS][GTHR]
    const int layer = blockIdx.y;
    const float4* __restrict__ base =
        reinterpret_cast<const float4*>(deltas + (size_t)layer * KK * NN);
    const int tid = threadIdx.x;
    const int n0 = blockIdx.x * GTHR + tid;

    uint32_t smem_base;
    {
        void* p = (void*)buf;
        smem_base = (uint32_t)__cvta_generic_to_shared(p);
    }

    float acc[NPAIR];
#pragma unroll
    for (int p = 0; p < NPAIR; p++) acc[p] = 0.0f;

    // Issue one half-stage (4 rows) of iteration `it`, close its commit group.
    auto issue_half = [&](int it, int half) {
        const int n = n0 + it * GSTRIDE;
        const int slot = (it % 3) * 2 + half;
#pragma unroll
        for (int r = 0; r < HROWS; r++) {
            const int j = half * HROWS + r;
            const uint32_t dst =
                smem_base + (uint32_t)(((slot * HROWS + r) * GTHR + tid) * 16);
            const float4* src = base + (size_t)j * R4C + n;
            asm volatile("cp.async.cg.shared.global [%0], [%1], 16;"
                         :: "r"(dst), "l"(src));
        }
        asm volatile("cp.async.commit_group;" ::: "memory");
    };

    // Prologue: iterations 0 and 1 fully issued (4 groups).
    issue_half(0, 0); issue_half(0, 1);
    issue_half(1, 0); issue_half(1, 1);

    for (int it = 0; it < GITERS; it++) {
        if (it + 2 < GITERS) {
            issue_half(it + 2, 0);
            issue_half(it + 2, 1);
        } else {
            // empty groups keep wait_group arithmetic uniform in the tail
            asm volatile("cp.async.commit_group;" ::: "memory");
            asm volatile("cp.async.commit_group;" ::: "memory");
        }
        // <=4 most recent groups pending => both groups of `it` are complete
        asm volatile("cp.async.wait_group 4;" ::: "memory");

        const int slot0 = (it % 3) * 2;
        float4 v[KK];
#pragma unroll
        for (int half = 0; half < 2; half++)
#pragma unroll
            for (int r = 0; r < HROWS; r++)
                v[half * HROWS + r] =
                    buf[((slot0 + half) * HROWS + r) * GTHR + tid];

        int p = 0;
#pragma unroll
        for (int i = 0; i < KK; i++)
#pragma unroll
            for (int j = i; j < KK; j++) {
                acc[p] += v[i].x * v[j].x + v[i].y * v[j].y +
                          v[i].z * v[j].z + v[i].w * v[j].w;
                p++;
            }
    }

    // Warp-level reduce each of the 36 accumulators.
#pragma unroll
    for (int p = 0; p < NPAIR; p++) {
        float a = acc[p];
#pragma unroll
        for (int o = 16; o > 0; o >>= 1)
            a += __shfl_down_sync(0xffffffffu, a, o);
        acc[p] = a;
    }

    // Recycle the (now dead) pipeline ring as cross-warp reduction scratch.
    __syncthreads();
    float* s_red = reinterpret_cast<float*>(buf);   // [4][NPAIR]
    const int wid = tid >> 5, lane = tid & 31;
    if (lane == 0) {
#pragma unroll
        for (int p = 0; p < NPAIR; p++) s_red[wid * NPAIR + p] = acc[p];
    }
    __syncthreads();

    if (tid < NPAIR) {
        float a = 0.0f;
#pragma unroll
        for (int w = 0; w < 4; w++) a += s_red[w * NPAIR + tid];
        g_part[layer][blockIdx.x][tid] = a;
    }
}

// ---------------------------------------------------------------------------
// Kernel 2: reduce partials -> logits -> softmax -> W = clip(beta)*attn + I.
// grid = LL, block = 64. Tiny.
// ---------------------------------------------------------------------------
__global__ __launch_bounds__(64) void finish_kernel(const float* __restrict__ beta) {
    const int layer = blockIdx.x;
    const int tid = threadIdx.x;
    __shared__ float gram[NPAIR];

    if (tid < NPAIR) {
        float a = 0.0f;
        for (int b = 0; b < GBLK; b++) a += g_part[layer][b][tid];
        gram[tid] = a;
    }
    __syncthreads();

    if (tid < KK) {
        const int k = tid;
        const float scale = rsqrtf((float)NN);   // N^-0.5
        float row[KK];
#pragma unroll
        for (int j = 0; j < KK; j++) {
            const int a = (k < j) ? k : j;
            const int b = (k < j) ? j : k;
            const int p = a * KK - (a * (a - 1)) / 2 + (b - a);
            row[j] = gram[p] * scale;
        }
        float m = row[0];
#pragma unroll
        for (int j = 1; j < KK; j++) m = fmaxf(m, row[j]);
        float s = 0.0f;
#pragma unroll
        for (int j = 0; j < KK; j++) { row[j] = expf(row[j] - m); s += row[j]; }
        const float inv = 1.0f / s;
        float b = beta[layer * KK + k];
        b = fminf(fmaxf(b, 0.0f), 1.0f);
#pragma unroll
        for (int j = 0; j < KK; j++)
            g_w[layer][k * KK + j] = b * row[j] * inv + ((j == k) ? 1.0f : 0.0f);
    }
}

// ---------------------------------------------------------------------------
// Kernel 3: out[l,k,n] = last[l,k,n] + sum_j W[l,k,j] * deltas[l,j,n]
// Proven config (~115.5us, ~6.65TB/s): batched 16 LDG.128, accumulate into
// last-regs, 8 stores; descending chunk order.
// grid = (OBLK, LL), block = 256.
// ---------------------------------------------------------------------------
__global__ __launch_bounds__(256, 2) void out_kernel(const float* __restrict__ last,
                                                     const float* __restrict__ deltas,
                                                     float* __restrict__ out) {
    const int layer = blockIdx.y;
    __shared__ float w[KK * KK];
    const int tid = threadIdx.x;
    if (tid < KK * KK) w[tid] = g_w[layer][tid];
    __syncthreads();

    const size_t off = (size_t)layer * KK * NN;
    const float4* __restrict__ d4 = reinterpret_cast<const float4*>(deltas + off);
    const float4* __restrict__ l4 = reinterpret_cast<const float4*>(last + off);
    float4* __restrict__ o4 = reinterpret_cast<float4*>(out + off);

    const int R = NN / 4;                 // 262144
    const int stride = OBLK * 256;        // 65536
    const int iters = R / stride;         // 4
    const int idx = blockIdx.x * 256 + tid;

#pragma unroll
    for (int it = iters - 1; it >= 0; it--) {   // descending chunks
        const int n4 = idx + it * stride;

        float4 d[KK];
        float4 a[KK];
#pragma unroll
        for (int j = 0; j < KK; j++)
            d[j] = d4[(size_t)j * R + n4];
#pragma unroll
        for (int k = 0; k < KK; k++)
            a[k] = l4[(size_t)k * R + n4];

#pragma unroll
        for (int k = 0; k < KK; k++) {
#pragma unroll
            for (int j = 0; j < KK; j++) {
                const float wv = w[k * KK + j];
                a[k].x = fmaf(wv, d[j].x, a[k].x);
                a[k].y = fmaf(wv, d[j].y, a[k].y);
                a[k].z = fmaf(wv, d[j].z, a[k].z);
                a[k].w = fmaf(wv, d[j].w, a[k].w);
            }
        }

#pragma unroll
        for (int k = 0; k < KK; k++)
            o4[(size_t)k * R + n4] = a[k];
    }
}

extern "C" void kernel_launch(void* const* d_in, const int* in_sizes, int n_in,
                              void* d_out, int out_size) {
    const float* last   = (const float*)d_in[0];
    const float* deltas = (const float*)d_in[1];
    const float* beta   = (const float*)d_in[2];
    float* out = (float*)d_out;

    const int gram_smem = 6 * HROWS * GTHR * 16;   // 49152B = 48KB exactly

    dim3 ggrid(GBLK, LL);
    gram_kernel<<<ggrid, GTHR, gram_smem>>>(deltas);

    finish_kernel<<<LL, 64>>>(beta);

    dim3 ogrid(OBLK, LL);
    out_kernel<<<ogrid, 256>>>(last, deltas, out);
}